// round 16
// baseline (speedup 1.0000x reference)
#include <cuda_runtime.h>
#include <cuda_bf16.h>
#include <math.h>
#include <stdint.h>

#define NN 50000
#define EE 800000
#define DD 128
#define HH 8
#define LL 3
#define SLOPE 0.2f
#define LN_EPS 1e-5f

#define XTILE 128
#define NTILES ((NN + XTILE - 1) / XTILE)   // 391
#define GEMM_CTAS 148

// ---------------- scratch (static device globals; no allocation allowed) ----
__device__ float g_h[NN * DD];        // evolving node features
__device__ float g_xl[NN * DD];       // h @ Wl
__device__ float g_xr[NN * DD];       // h @ Wr
__device__ int   g_deg[NN];
__device__ int   g_row[NN + 1];
__device__ int   g_cur[NN];
__device__ int   g_csr[EE];

// ---------------- helpers ---------------------------------------------------
__device__ __forceinline__ float lrelu(float x) { return x > 0.f ? x : SLOPE * x; }

// packed dual-fp32 FMA (Blackwell FFMA2; only reachable via PTX)
#define FMA_F32X2(d, a, b, c) \
    asm("fma.rn.f32x2 %0, %1, %2, %3;" : "=l"(d) : "l"(a), "l"(b), "l"(c))
#define PACK_DUP_F32X2(out, v) \
    asm("mov.b64 %0, {%1, %1};" : "=l"(out) : "f"(v))
#define UNPACK_F32X2(lo, hi, in) \
    asm("mov.b64 {%0, %1}, %2;" : "=f"(lo), "=f"(hi) : "l"(in))

// ---------------- CSR build (once per launch) --------------------------------
__global__ void hist_kernel(const int* __restrict__ ei) {
    int e = blockIdx.x * blockDim.x + threadIdx.x;
    if (e < EE) atomicAdd(&g_deg[__ldg(ei + EE + e)], 1);
}

#define SCAN_THREADS 1024
#define SCAN_PER 49
__global__ void scan_kernel() {
    int tid = threadIdx.x;
    int start = tid * SCAN_PER;
    int end = start + SCAN_PER; if (end > NN) end = NN;
    int s = 0;
    for (int i = start; i < end; i++) s += g_deg[i];

    int lane = tid & 31, wid = tid >> 5;
    int incl = s;
#pragma unroll
    for (int o = 1; o < 32; o <<= 1) {
        int u = __shfl_up_sync(0xffffffffu, incl, o);
        if (lane >= o) incl += u;
    }
    __shared__ int wsum[32];
    if (lane == 31) wsum[wid] = incl;
    __syncthreads();
    if (wid == 0) {
        int w = wsum[lane];
#pragma unroll
        for (int o = 1; o < 32; o <<= 1) {
            int u = __shfl_up_sync(0xffffffffu, w, o);
            if (lane >= o) w += u;
        }
        wsum[lane] = w;
    }
    __syncthreads();
    int excl = incl - s + (wid > 0 ? wsum[wid - 1] : 0);
    int run = excl;
    for (int i = start; i < end; i++) {
        g_row[i] = run;
        g_cur[i] = run;
        run += g_deg[i];
    }
    if (tid == 0) g_row[NN] = EE;
}

__global__ void fill_kernel(const int* __restrict__ ei) {
    int e = blockIdx.x * blockDim.x + threadIdx.x;
    if (e < EE) {
        int dst = __ldg(ei + EE + e);
        int p = atomicAdd(&g_cur[dst], 1);
        g_csr[p] = __ldg(ei + e);
    }
}

// ---------------- persistent dual GEMM, row-pair FFMA2, 1024 thr ------------
// (round-13 version — measured best: 78.4us)
#define SMEM_FLOATS (3 * 128 * 128)

__global__ __launch_bounds__(1024, 1) void gemm_persist(const float* __restrict__ X,
                                                        const float* __restrict__ Wl,
                                                        const float* __restrict__ Wr) {
    extern __shared__ float smem[];
    float* Wls = smem;              // [k*128 + c]
    float* Wrs = smem + 16384;
    float* Xs  = smem + 32768;      // [k*128 + row]  (transposed)

    int tid = threadIdx.x;
    int half = tid >> 9;            // 0: xl, 1: xr
    int htid = tid & 511;
    int tx = htid & 31;             // col group: 4 cols
    int ty = htid >> 5;             // row group: 8 rows (4 pairs), 0..15

    const float* Ws = half ? Wrs : Wls;
    float* Yout = half ? g_xr : g_xl;

    for (int i = tid * 4; i < 16384; i += 4096) {
        *(float4*)(Wls + i) = *(const float4*)(Wl + i);
        *(float4*)(Wrs + i) = *(const float4*)(Wr + i);
    }
    __syncthreads();

    int xrow = tid & 127;
    int kq   = (tid >> 7) * 16;

    for (int tile = blockIdx.x; tile < NTILES; tile += GEMM_CTAS) {
        int row0 = tile * XTILE;
        {
            int gr = row0 + xrow;
#pragma unroll
            for (int k = 0; k < 16; k += 4) {
                float4 v = make_float4(0.f, 0.f, 0.f, 0.f);
                if (gr < NN) v = *(const float4*)(X + (size_t)gr * 128 + kq + k);
                Xs[(kq + k + 0) * 128 + xrow] = v.x;
                Xs[(kq + k + 1) * 128 + xrow] = v.y;
                Xs[(kq + k + 2) * 128 + xrow] = v.z;
                Xs[(kq + k + 3) * 128 + xrow] = v.w;
            }
        }
        __syncthreads();

        unsigned long long acc[4][4];
#pragma unroll
        for (int p = 0; p < 4; p++)
#pragma unroll
            for (int j = 0; j < 4; j++) acc[p][j] = 0ull;

#pragma unroll 4
        for (int kk = 0; kk < 128; kk++) {
            const unsigned long long* arow =
                (const unsigned long long*)(&Xs[kk * 128 + ty * 8]);
            ulonglong2 a01 = *(const ulonglong2*)(arow + 0);
            ulonglong2 a23 = *(const ulonglong2*)(arow + 2);
            unsigned long long ap[4] = {a01.x, a01.y, a23.x, a23.y};
            float4 bv = *(const float4*)(&Ws[kk * 128 + tx * 4]);
            unsigned long long bb[4];
            PACK_DUP_F32X2(bb[0], bv.x);
            PACK_DUP_F32X2(bb[1], bv.y);
            PACK_DUP_F32X2(bb[2], bv.z);
            PACK_DUP_F32X2(bb[3], bv.w);
#pragma unroll
            for (int p = 0; p < 4; p++)
#pragma unroll
                for (int j = 0; j < 4; j++)
                    FMA_F32X2(acc[p][j], ap[p], bb[j], acc[p][j]);
        }

#pragma unroll
        for (int p = 0; p < 4; p++) {
            float lo[4], hi[4];
#pragma unroll
            for (int j = 0; j < 4; j++) UNPACK_F32X2(lo[j], hi[j], acc[p][j]);
            int gr0 = row0 + ty * 8 + 2 * p;
            if (gr0 < NN)
                *(float4*)(Yout + (size_t)gr0 * 128 + tx * 4) =
                    make_float4(lo[0], lo[1], lo[2], lo[3]);
            if (gr0 + 1 < NN)
                *(float4*)(Yout + (size_t)(gr0 + 1) * 128 + tx * 4) =
                    make_float4(hi[0], hi[1], hi[2], hi[3]);
        }
        __syncthreads();
    }
}

// ---------------- CSR edge pass: TWO warps per node (64 ch each) ------------
// Warp pair (2w, 2w+1): half 0 -> channels 0..63 (heads 0-3), half 1 -> 64..127.
// Each warp walks the full edge list gathering its 256B half-row; softmax denom
// is fully warp-local (head groups = 8 lanes, 3 shfl reduce). Only LayerNorm
// couples the halves (two smem exchanges). Block = 8 warps = 4 nodes.
__global__ __launch_bounds__(256) void edge_csr(const float* __restrict__ att_l,
                                                const float* __restrict__ bias_l,
                                                const float* __restrict__ gamma_l,
                                                const float* __restrict__ beta_l,
                                                const float* __restrict__ resid,
                                                float* __restrict__ final_out) {
    int wid = threadIdx.x >> 5;
    int n = blockIdx.x * 4 + (wid >> 1);     // grid = NN/4 exactly
    int lane = threadIdx.x & 31;
    int half = wid & 1;
    int c0 = half * 64 + lane * 2;

    float2 xr = *(const float2*)(g_xr + (size_t)n * 128 + c0);
    float2 t  = *(const float2*)(att_l + c0);

    // self-loop
    float2 a = *(const float2*)(g_xl + (size_t)n * 128 + c0);
    float s = lrelu(a.x + xr.x) * t.x + lrelu(a.y + xr.y) * t.y;
    s += __shfl_xor_sync(0xffffffffu, s, 1);
    s += __shfl_xor_sync(0xffffffffu, s, 2);
    s += __shfl_xor_sync(0xffffffffu, s, 4);
    float v = __expf(s);
    float2 acc = make_float2(v * a.x, v * a.y);
    float denom = v;

    int i = g_row[n];
    int endi = g_row[n + 1];

    // 4-way unrolled: 4 independent half-row gathers in flight
    for (; i + 3 < endi; i += 4) {
        int s0 = __ldg(g_csr + i);
        int s1 = __ldg(g_csr + i + 1);
        int s2 = __ldg(g_csr + i + 2);
        int s3 = __ldg(g_csr + i + 3);
        float2 a0 = *(const float2*)(g_xl + (size_t)s0 * 128 + c0);
        float2 a1 = *(const float2*)(g_xl + (size_t)s1 * 128 + c0);
        float2 a2 = *(const float2*)(g_xl + (size_t)s2 * 128 + c0);
        float2 a3 = *(const float2*)(g_xl + (size_t)s3 * 128 + c0);
        float l0 = lrelu(a0.x + xr.x) * t.x + lrelu(a0.y + xr.y) * t.y;
        float l1 = lrelu(a1.x + xr.x) * t.x + lrelu(a1.y + xr.y) * t.y;
        float l2 = lrelu(a2.x + xr.x) * t.x + lrelu(a2.y + xr.y) * t.y;
        float l3 = lrelu(a3.x + xr.x) * t.x + lrelu(a3.y + xr.y) * t.y;
        l0 += __shfl_xor_sync(0xffffffffu, l0, 1);
        l0 += __shfl_xor_sync(0xffffffffu, l0, 2);
        l0 += __shfl_xor_sync(0xffffffffu, l0, 4);
        l1 += __shfl_xor_sync(0xffffffffu, l1, 1);
        l1 += __shfl_xor_sync(0xffffffffu, l1, 2);
        l1 += __shfl_xor_sync(0xffffffffu, l1, 4);
        l2 += __shfl_xor_sync(0xffffffffu, l2, 1);
        l2 += __shfl_xor_sync(0xffffffffu, l2, 2);
        l2 += __shfl_xor_sync(0xffffffffu, l2, 4);
        l3 += __shfl_xor_sync(0xffffffffu, l3, 1);
        l3 += __shfl_xor_sync(0xffffffffu, l3, 2);
        l3 += __shfl_xor_sync(0xffffffffu, l3, 4);
        float v0 = __expf(l0);
        float v1 = __expf(l1);
        float v2 = __expf(l2);
        float v3 = __expf(l3);
        acc.x += v0 * a0.x + v1 * a1.x + v2 * a2.x + v3 * a3.x;
        acc.y += v0 * a0.y + v1 * a1.y + v2 * a2.y + v3 * a3.y;
        denom += v0 + v1 + v2 + v3;
    }
    for (; i < endi; i++) {
        int s0 = __ldg(g_csr + i);
        float2 a0 = *(const float2*)(g_xl + (size_t)s0 * 128 + c0);
        float l0 = lrelu(a0.x + xr.x) * t.x + lrelu(a0.y + xr.y) * t.y;
        l0 += __shfl_xor_sync(0xffffffffu, l0, 1);
        l0 += __shfl_xor_sync(0xffffffffu, l0, 2);
        l0 += __shfl_xor_sync(0xffffffffu, l0, 4);
        float v0 = __expf(l0);
        acc.x += v0 * a0.x;
        acc.y += v0 * a0.y;
        denom += v0;
    }

    // normalize + bias
    float inv_d = 1.f / denom;
    float2 bi = *(const float2*)(bias_l + c0);
    float yx = acc.x * inv_d + bi.x;
    float yy = acc.y * inv_d + bi.y;

    // LayerNorm across 128 channels: warp-local sum, then pair exchange
    __shared__ float ssum[8];
    __shared__ float svar[8];

    float ps = yx + yy;
#pragma unroll
    for (int o = 16; o; o >>= 1) ps += __shfl_xor_sync(0xffffffffu, ps, o);
    if (lane == 0) ssum[wid] = ps;
    __syncthreads();
    float mu = (ssum[wid] + ssum[wid ^ 1]) * (1.f / 128.f);

    float dx = yx - mu, dy = yy - mu;
    float pv = dx * dx + dy * dy;
#pragma unroll
    for (int o = 16; o; o >>= 1) pv += __shfl_xor_sync(0xffffffffu, pv, o);
    if (lane == 0) svar[wid] = pv;
    __syncthreads();
    float rstd = rsqrtf((svar[wid] + svar[wid ^ 1]) * (1.f / 128.f) + LN_EPS);

    float2 g  = *(const float2*)(gamma_l + c0);
    float2 bb = *(const float2*)(beta_l + c0);
    float2 hv = *(const float2*)(resid + (size_t)n * 128 + c0);

    float tt;
    float2 r;
    tt = dx * rstd * g.x + bb.x; r.x = hv.x + (tt > 0.f ? tt : expm1f(tt));
    tt = dy * rstd * g.y + bb.y; r.y = hv.y + (tt > 0.f ? tt : expm1f(tt));

    *(float2*)(g_h + (size_t)n * 128 + c0) = r;
    if (final_out) *(float2*)(final_out + (size_t)n * 128 + c0) = r;
}

// ---------------- host orchestration ----------------------------------------
extern "C" void kernel_launch(void* const* d_in, const int* in_sizes, int n_in,
                              void* d_out, int out_size) {
    const float* x     = (const float*)d_in[0];
    const float* Wl    = (const float*)d_in[1];
    const float* Wr    = (const float*)d_in[2];
    const float* att   = (const float*)d_in[3];
    const float* bias  = (const float*)d_in[4];
    const float* gamma = (const float*)d_in[5];
    const float* beta  = (const float*)d_in[6];
    const int*   ei    = (const int*)d_in[7];
    float* out = (float*)d_out;

    void* deg_ptr = nullptr;
    void* h_ptr = nullptr;
    cudaGetSymbolAddress(&deg_ptr, g_deg);
    cudaGetSymbolAddress(&h_ptr, g_h);

    const int smem_bytes = SMEM_FLOATS * sizeof(float);   // 196608
    cudaFuncSetAttribute(gemm_persist,
                         cudaFuncAttributeMaxDynamicSharedMemorySize, smem_bytes);

    // build CSR (dst -> list of src), once per launch
    cudaMemsetAsync(deg_ptr, 0, NN * sizeof(int));
    hist_kernel<<<(EE + 255) / 256, 256>>>(ei);
    scan_kernel<<<1, SCAN_THREADS>>>();
    fill_kernel<<<(EE + 255) / 256, 256>>>(ei);

    const int node_grid = NN / 4;   // 12500, exact

    for (int l = 0; l < LL; l++) {
        const float* X = (l == 0) ? x : (const float*)h_ptr;
        gemm_persist<<<GEMM_CTAS, 1024, smem_bytes>>>(X, Wl + (size_t)l * DD * DD,
                                                      Wr + (size_t)l * DD * DD);
        edge_csr<<<node_grid, 256>>>(att + l * HH * 16, bias + l * DD,
                                     gamma + l * DD, beta + l * DD, X,
                                     (l == LL - 1) ? out : nullptr);
    }
}

// round 17
// speedup vs baseline: 1.2333x; 1.2333x over previous
#include <cuda_runtime.h>
#include <cuda_bf16.h>
#include <math.h>
#include <stdint.h>

#define NN 50000
#define EE 800000
#define DD 128
#define HH 8
#define LL 3
#define SLOPE 0.2f
#define LN_EPS 1e-5f

#define XTILE 114
#define NTILES ((NN + XTILE - 1) / XTILE)   // 439 <= 3*148 -> critical path 3 tiles
#define GEMM_CTAS 148

// ---------------- scratch (static device globals; no allocation allowed) ----
__device__ float g_h[NN * DD];        // evolving node features
__device__ float g_xl[NN * DD];       // h @ Wl
__device__ float g_xr[NN * DD];       // h @ Wr
__device__ int   g_deg[NN];
__device__ int   g_row[NN + 1];
__device__ int   g_cur[NN];
__device__ int   g_csr[EE];

// ---------------- helpers ---------------------------------------------------
__device__ __forceinline__ float lrelu(float x) { return x > 0.f ? x : SLOPE * x; }

// packed dual-fp32 FMA (Blackwell FFMA2; only reachable via PTX)
#define FMA_F32X2(d, a, b, c) \
    asm("fma.rn.f32x2 %0, %1, %2, %3;" : "=l"(d) : "l"(a), "l"(b), "l"(c))
#define PACK_DUP_F32X2(out, v) \
    asm("mov.b64 %0, {%1, %1};" : "=l"(out) : "f"(v))
#define UNPACK_F32X2(lo, hi, in) \
    asm("mov.b64 {%0, %1}, %2;" : "=f"(lo), "=f"(hi) : "l"(in))

// ---------------- CSR build (once per launch) --------------------------------
__global__ void hist_kernel(const int* __restrict__ ei) {
    int e = blockIdx.x * blockDim.x + threadIdx.x;
    if (e < EE) atomicAdd(&g_deg[__ldg(ei + EE + e)], 1);
}

#define SCAN_THREADS 1024
#define SCAN_PER 49
__global__ void scan_kernel() {
    int tid = threadIdx.x;
    int start = tid * SCAN_PER;
    int end = start + SCAN_PER; if (end > NN) end = NN;
    int s = 0;
    for (int i = start; i < end; i++) s += g_deg[i];

    int lane = tid & 31, wid = tid >> 5;
    int incl = s;
#pragma unroll
    for (int o = 1; o < 32; o <<= 1) {
        int u = __shfl_up_sync(0xffffffffu, incl, o);
        if (lane >= o) incl += u;
    }
    __shared__ int wsum[32];
    if (lane == 31) wsum[wid] = incl;
    __syncthreads();
    if (wid == 0) {
        int w = wsum[lane];
#pragma unroll
        for (int o = 1; o < 32; o <<= 1) {
            int u = __shfl_up_sync(0xffffffffu, w, o);
            if (lane >= o) w += u;
        }
        wsum[lane] = w;
    }
    __syncthreads();
    int excl = incl - s + (wid > 0 ? wsum[wid - 1] : 0);
    int run = excl;
    for (int i = start; i < end; i++) {
        g_row[i] = run;
        g_cur[i] = run;
        run += g_deg[i];
    }
    if (tid == 0) g_row[NN] = EE;
}

__global__ void fill_kernel(const int* __restrict__ ei) {
    int e = blockIdx.x * blockDim.x + threadIdx.x;
    if (e < EE) {
        int dst = __ldg(ei + EE + e);
        int p = atomicAdd(&g_cur[dst], 1);
        g_csr[p] = __ldg(ei + e);
    }
}

// ---------------- persistent dual GEMM, row-pair FFMA2, 1024 thr ------------
// grid=148, block=1024. Threads [0,512) compute xl (Wls); [512,1024) xr (Wrs).
// Per thread: 8 rows (4 row-pairs, native u64 A) x 4 cols (dup'd B).
// XTILE=114 balances the persistent loop (439 tiles -> max 3 per CTA, 342-row
// critical path vs 384 at XTILE=128). Loads cover rows 0..127 of each tile
// window (no guard needed: overlap rows are valid memory, their accumulators
// are never stored); stores are guarded by row < XTILE.
// smem: Wls[16384] | Wrs[16384] | Xs[16384] (transposed [k][row]) = 192KB
#define SMEM_FLOATS (3 * 128 * 128)

__global__ __launch_bounds__(1024, 1) void gemm_persist(const float* __restrict__ X,
                                                        const float* __restrict__ Wl,
                                                        const float* __restrict__ Wr) {
    extern __shared__ float smem[];
    float* Wls = smem;              // [k*128 + c]
    float* Wrs = smem + 16384;
    float* Xs  = smem + 32768;      // [k*128 + row]  (transposed)

    int tid = threadIdx.x;
    int half = tid >> 9;            // 0: xl, 1: xr
    int htid = tid & 511;
    int tx = htid & 31;             // col group: 4 cols
    int ty = htid >> 5;             // row group: 8 rows (4 pairs), 0..15

    const float* Ws = half ? Wrs : Wls;
    float* Yout = half ? g_xr : g_xl;

    // ---- load both W matrices once ----
    for (int i = tid * 4; i < 16384; i += 4096) {
        *(float4*)(Wls + i) = *(const float4*)(Wl + i);
        *(float4*)(Wrs + i) = *(const float4*)(Wr + i);
    }
    __syncthreads();

    int xrow = tid & 127;
    int kq   = (tid >> 7) * 16;     // eighth of the k-range per thread

    for (int tile = blockIdx.x; tile < NTILES; tile += GEMM_CTAS) {
        int row0 = tile * XTILE;

        // ---- load X window (128 rows x 128 k), store transposed ----
        {
            int gr = row0 + xrow;
#pragma unroll
            for (int k = 0; k < 16; k += 4) {
                float4 v = make_float4(0.f, 0.f, 0.f, 0.f);
                if (gr < NN) v = *(const float4*)(X + (size_t)gr * 128 + kq + k);
                Xs[(kq + k + 0) * 128 + xrow] = v.x;
                Xs[(kq + k + 1) * 128 + xrow] = v.y;
                Xs[(kq + k + 2) * 128 + xrow] = v.z;
                Xs[(kq + k + 3) * 128 + xrow] = v.w;
            }
        }
        __syncthreads();

        unsigned long long acc[4][4];   // [row-pair][col]
#pragma unroll
        for (int p = 0; p < 4; p++)
#pragma unroll
            for (int j = 0; j < 4; j++) acc[p][j] = 0ull;

#pragma unroll 4
        for (int kk = 0; kk < 128; kk++) {
            // A: 4 native row-pair u64s (broadcast across warp: ty uniform)
            const unsigned long long* arow =
                (const unsigned long long*)(&Xs[kk * 128 + ty * 8]);
            ulonglong2 a01 = *(const ulonglong2*)(arow + 0);
            ulonglong2 a23 = *(const ulonglong2*)(arow + 2);
            unsigned long long ap[4] = {a01.x, a01.y, a23.x, a23.y};
            // B: 4 cols, coalesced LDS.128, then duplicate
            float4 bv = *(const float4*)(&Ws[kk * 128 + tx * 4]);
            unsigned long long bb[4];
            PACK_DUP_F32X2(bb[0], bv.x);
            PACK_DUP_F32X2(bb[1], bv.y);
            PACK_DUP_F32X2(bb[2], bv.z);
            PACK_DUP_F32X2(bb[3], bv.w);
#pragma unroll
            for (int p = 0; p < 4; p++)
#pragma unroll
                for (int j = 0; j < 4; j++)
                    FMA_F32X2(acc[p][j], ap[p], bb[j], acc[p][j]);
        }

        // ---- store: pair p = rows (ty*8+2p, +1); only rows < XTILE ----
#pragma unroll
        for (int p = 0; p < 4; p++) {
            int r0 = ty * 8 + 2 * p;
            if (r0 < XTILE) {
                float lo[4], hi[4];
#pragma unroll
                for (int j = 0; j < 4; j++) UNPACK_F32X2(lo[j], hi[j], acc[p][j]);
                int gr0 = row0 + r0;
                if (gr0 < NN)
                    *(float4*)(Yout + (size_t)gr0 * 128 + tx * 4) =
                        make_float4(lo[0], lo[1], lo[2], lo[3]);
                if (gr0 + 1 < NN)
                    *(float4*)(Yout + (size_t)(gr0 + 1) * 128 + tx * 4) =
                        make_float4(hi[0], hi[1], hi[2], hi[3]);
            }
        }
        __syncthreads();   // protect Xs before next tile's overwrite
    }
}

// ---------------- CSR edge pass + softmax + LN + ELU + residual -------------
// (round-13 4-way __ldg unroll — measured best)
__global__ __launch_bounds__(256) void edge_csr(const float* __restrict__ att_l,
                                                const float* __restrict__ bias_l,
                                                const float* __restrict__ gamma_l,
                                                const float* __restrict__ beta_l,
                                                const float* __restrict__ resid,
                                                float* __restrict__ final_out) {
    int n = blockIdx.x * 8 + (threadIdx.x >> 5);
    if (n >= NN) return;
    int lane = threadIdx.x & 31;
    int c0 = lane * 4;

    float4 xr = *(const float4*)(g_xr + (size_t)n * 128 + c0);
    float4 t  = *(const float4*)(att_l + c0);

    // self-loop
    float4 a = *(const float4*)(g_xl + (size_t)n * 128 + c0);
    float s = lrelu(a.x + xr.x) * t.x + lrelu(a.y + xr.y) * t.y +
              lrelu(a.z + xr.z) * t.z + lrelu(a.w + xr.w) * t.w;
    s += __shfl_xor_sync(0xffffffffu, s, 1);
    s += __shfl_xor_sync(0xffffffffu, s, 2);
    float v = __expf(s);
    float4 acc = make_float4(v * a.x, v * a.y, v * a.z, v * a.w);
    float denom = v;

    int i = g_row[n];
    int endi = g_row[n + 1];

    // 4-way unrolled: 4 independent gathers in flight
    for (; i + 3 < endi; i += 4) {
        int s0 = __ldg(g_csr + i);
        int s1 = __ldg(g_csr + i + 1);
        int s2 = __ldg(g_csr + i + 2);
        int s3 = __ldg(g_csr + i + 3);
        float4 a0 = *(const float4*)(g_xl + (size_t)s0 * 128 + c0);
        float4 a1 = *(const float4*)(g_xl + (size_t)s1 * 128 + c0);
        float4 a2 = *(const float4*)(g_xl + (size_t)s2 * 128 + c0);
        float4 a3 = *(const float4*)(g_xl + (size_t)s3 * 128 + c0);
        float l0 = lrelu(a0.x + xr.x) * t.x + lrelu(a0.y + xr.y) * t.y +
                   lrelu(a0.z + xr.z) * t.z + lrelu(a0.w + xr.w) * t.w;
        float l1 = lrelu(a1.x + xr.x) * t.x + lrelu(a1.y + xr.y) * t.y +
                   lrelu(a1.z + xr.z) * t.z + lrelu(a1.w + xr.w) * t.w;
        float l2 = lrelu(a2.x + xr.x) * t.x + lrelu(a2.y + xr.y) * t.y +
                   lrelu(a2.z + xr.z) * t.z + lrelu(a2.w + xr.w) * t.w;
        float l3 = lrelu(a3.x + xr.x) * t.x + lrelu(a3.y + xr.y) * t.y +
                   lrelu(a3.z + xr.z) * t.z + lrelu(a3.w + xr.w) * t.w;
        l0 += __shfl_xor_sync(0xffffffffu, l0, 1);
        l0 += __shfl_xor_sync(0xffffffffu, l0, 2);
        l1 += __shfl_xor_sync(0xffffffffu, l1, 1);
        l1 += __shfl_xor_sync(0xffffffffu, l1, 2);
        l2 += __shfl_xor_sync(0xffffffffu, l2, 1);
        l2 += __shfl_xor_sync(0xffffffffu, l2, 2);
        l3 += __shfl_xor_sync(0xffffffffu, l3, 1);
        l3 += __shfl_xor_sync(0xffffffffu, l3, 2);
        float v0 = __expf(l0);
        float v1 = __expf(l1);
        float v2 = __expf(l2);
        float v3 = __expf(l3);
        acc.x += v0 * a0.x + v1 * a1.x + v2 * a2.x + v3 * a3.x;
        acc.y += v0 * a0.y + v1 * a1.y + v2 * a2.y + v3 * a3.y;
        acc.z += v0 * a0.z + v1 * a1.z + v2 * a2.z + v3 * a3.z;
        acc.w += v0 * a0.w + v1 * a1.w + v2 * a2.w + v3 * a3.w;
        denom += v0 + v1 + v2 + v3;
    }
    for (; i < endi; i++) {
        int s0 = __ldg(g_csr + i);
        float4 a0 = *(const float4*)(g_xl + (size_t)s0 * 128 + c0);
        float l0 = lrelu(a0.x + xr.x) * t.x + lrelu(a0.y + xr.y) * t.y +
                   lrelu(a0.z + xr.z) * t.z + lrelu(a0.w + xr.w) * t.w;
        l0 += __shfl_xor_sync(0xffffffffu, l0, 1);
        l0 += __shfl_xor_sync(0xffffffffu, l0, 2);
        float v0 = __expf(l0);
        acc.x += v0 * a0.x;
        acc.y += v0 * a0.y;
        acc.z += v0 * a0.z;
        acc.w += v0 * a0.w;
        denom += v0;
    }

    float inv_d = 1.f / denom;
    float4 bi = *(const float4*)(bias_l + c0);
    float4 y;
    y.x = acc.x * inv_d + bi.x;
    y.y = acc.y * inv_d + bi.y;
    y.z = acc.z * inv_d + bi.z;
    y.w = acc.w * inv_d + bi.w;

    float sum = y.x + y.y + y.z + y.w;
#pragma unroll
    for (int o = 16; o; o >>= 1) sum += __shfl_xor_sync(0xffffffffu, sum, o);
    float mu = sum * (1.f / 128.f);

    float dx = y.x - mu, dy = y.y - mu, dz = y.z - mu, dw = y.w - mu;
    float vs = dx * dx + dy * dy + dz * dz + dw * dw;
#pragma unroll
    for (int o = 16; o; o >>= 1) vs += __shfl_xor_sync(0xffffffffu, vs, o);
    float rstd = rsqrtf(vs * (1.f / 128.f) + LN_EPS);

    float4 g  = *(const float4*)(gamma_l + c0);
    float4 bb = *(const float4*)(beta_l + c0);
    float4 hv = *(const float4*)(resid + (size_t)n * 128 + c0);

    float tt;
    float4 r;
    tt = dx * rstd * g.x + bb.x; r.x = hv.x + (tt > 0.f ? tt : expm1f(tt));
    tt = dy * rstd * g.y + bb.y; r.y = hv.y + (tt > 0.f ? tt : expm1f(tt));
    tt = dz * rstd * g.z + bb.z; r.z = hv.z + (tt > 0.f ? tt : expm1f(tt));
    tt = dw * rstd * g.w + bb.w; r.w = hv.w + (tt > 0.f ? tt : expm1f(tt));

    *(float4*)(g_h + (size_t)n * 128 + c0) = r;
    if (final_out) *(float4*)(final_out + (size_t)n * 128 + c0) = r;
}

// ---------------- host orchestration ----------------------------------------
extern "C" void kernel_launch(void* const* d_in, const int* in_sizes, int n_in,
                              void* d_out, int out_size) {
    const float* x     = (const float*)d_in[0];
    const float* Wl    = (const float*)d_in[1];
    const float* Wr    = (const float*)d_in[2];
    const float* att   = (const float*)d_in[3];
    const float* bias  = (const float*)d_in[4];
    const float* gamma = (const float*)d_in[5];
    const float* beta  = (const float*)d_in[6];
    const int*   ei    = (const int*)d_in[7];
    float* out = (float*)d_out;

    void* deg_ptr = nullptr;
    void* h_ptr = nullptr;
    cudaGetSymbolAddress(&deg_ptr, g_deg);
    cudaGetSymbolAddress(&h_ptr, g_h);

    const int smem_bytes = SMEM_FLOATS * sizeof(float);   // 196608
    cudaFuncSetAttribute(gemm_persist,
                         cudaFuncAttributeMaxDynamicSharedMemorySize, smem_bytes);

    // build CSR (dst -> list of src), once per launch
    cudaMemsetAsync(deg_ptr, 0, NN * sizeof(int));
    hist_kernel<<<(EE + 255) / 256, 256>>>(ei);
    scan_kernel<<<1, SCAN_THREADS>>>();
    fill_kernel<<<(EE + 255) / 256, 256>>>(ei);

    const int node_grid = (NN + 7) / 8;

    for (int l = 0; l < LL; l++) {
        const float* X = (l == 0) ? x : (const float*)h_ptr;
        gemm_persist<<<GEMM_CTAS, 1024, smem_bytes>>>(X, Wl + (size_t)l * DD * DD,
                                                      Wr + (size_t)l * DD * DD);
        edge_csr<<<node_grid, 256>>>(att + l * HH * 16, bias + l * DD,
                                     gamma + l * DD, beta + l * DD, X,
                                     (l == LL - 1) ? out : nullptr);
    }
}